// round 6
// baseline (speedup 1.0000x reference)
#include <cuda_runtime.h>
#include <cuda_bf16.h>
#include <math.h>

// ---------------- problem constants ----------------
#define NN    50000
#define EE    800000
#define FF    128
#define HH    4
#define CC    32
#define HCW   128
#define LINW  256
#define OUTW  10
#define GG    64
#define ETOT  (EE + NN)     // edges + self loops
#define NEG   0.2f

// ---------------- device scratch (no allocation allowed) ----------------
__device__ float    g_h[NN * HCW];       // per-layer transformed features h = in @ W
__device__ float    g_out[NN * HCW];     // aggregated output (next layer's input)
__device__ float    g_asrc[NN * HH];
__device__ float    g_adst[NN * HH];
__device__ unsigned g_emaxu[NN * HH];    // monotone-encoded float for atomicMax
__device__ float    g_denom[NN * HH];
__device__ float    g_pool[GG * HCW];
__device__ float    g_z[GG * LINW];
__device__ int      g_is64;

// ---------------- helpers ----------------
__device__ __forceinline__ float lrelu(float x) { return x > 0.f ? x : NEG * x; }

// monotone order-preserving float<->uint map (handles negatives) for atomicMax
__device__ __forceinline__ unsigned fenc(float f) {
    unsigned u = __float_as_uint(f);
    return (u & 0x80000000u) ? ~u : (u | 0x80000000u);
}
__device__ __forceinline__ float fdec(unsigned u) {
    return __uint_as_float((u & 0x80000000u) ? (u & 0x7fffffffu) : ~u);
}
#define ENC_NEGINF 0x007fffffu   // fenc(-inf)

__device__ __forceinline__ void edge_sd(const void* __restrict__ ei, int e, int is64,
                                        int& s, int& d) {
    if (e < EE) {
        if (is64) {
            const long long* p = (const long long*)ei;
            s = (int)p[e]; d = (int)p[EE + e];
        } else {
            const int* p = (const int*)ei;
            s = p[e]; d = p[EE + e];
        }
    } else {
        s = d = e - EE;   // self loop
    }
}

__device__ __forceinline__ void red_add_v4(float* p, float a, float b, float c, float d) {
    asm volatile("red.global.add.v4.f32 [%0], {%1,%2,%3,%4};"
                 :: "l"(p), "f"(a), "f"(b), "f"(c), "f"(d) : "memory");
}

// ---------------- dtype detection (int64 vs int32 indices) ----------------
__global__ void k_detect(const unsigned* __restrict__ ei_words) {
    // int64 little-endian with values < 2^31 -> all odd words are zero.
    unsigned acc = 0;
    for (int i = 1; i < 256; i += 2) acc |= ei_words[i];
    g_is64 = (acc == 0u) ? 1 : 0;
}

__global__ void k_initpool() {
    int i = blockIdx.x * blockDim.x + threadIdx.x;
    if (i < GG * HCW) g_pool[i] = 0.f;
}

// ---------------- GEMM: h = f(in) @ W, f = identity or relu(x + bias_prev) ----------------
// Block: 256 threads, 64 rows x 128 cols tile. Two K-panels of 64 so static smem = 48KB.
__global__ __launch_bounds__(256) void k_gemm(const float* __restrict__ inp,
                                              const float* __restrict__ W,
                                              const float* __restrict__ bias,
                                              int use_gout) {
    __shared__ float Ws[64 * 128];   // 32 KB : k-panel x all cols
    __shared__ float Xs[64 * 64];    // 16 KB : 64 rows x 64 k

    const float* in = use_gout ? g_out : inp;
    const int tid  = threadIdx.x;
    const int r0   = blockIdx.x * 64;
    const int colg = tid & 31;       // 4 cols: colg*4 .. colg*4+3
    const int rowg = tid >> 5;       // 8 rows: rowg*8 .. rowg*8+7

    float4* Ws4 = (float4*)Ws;
    float4* Xs4 = (float4*)Xs;
    const float4* W4  = (const float4*)W;
    const float4* in4 = (const float4*)in;
    const float4* b4  = (const float4*)bias;

    float4 acc[8];
#pragma unroll
    for (int r = 0; r < 8; r++) acc[r] = make_float4(0.f, 0.f, 0.f, 0.f);

    for (int kk = 0; kk < 128; kk += 64) {
        // load W panel: 64x128 floats = 2048 float4
        for (int i = tid; i < 2048; i += 256) Ws4[i] = W4[kk * 32 + i];
        // load X panel: 64 rows x 16 float4
        for (int i = tid; i < 1024; i += 256) {
            int row = i >> 4, kc = i & 15;
            int gr = r0 + row;
            float4 v = make_float4(0.f, 0.f, 0.f, 0.f);
            if (gr < NN) {
                v = in4[gr * 32 + (kk >> 2) + kc];
                if (bias) {
                    float4 bb = b4[(kk >> 2) + kc];
                    v.x = fmaxf(v.x + bb.x, 0.f);
                    v.y = fmaxf(v.y + bb.y, 0.f);
                    v.z = fmaxf(v.z + bb.z, 0.f);
                    v.w = fmaxf(v.w + bb.w, 0.f);
                }
            }
            Xs4[i] = v;
        }
        __syncthreads();

        for (int k = 0; k < 64; k++) {
            float4 w = Ws4[k * 32 + colg];
#pragma unroll
            for (int r = 0; r < 8; r++) {
                float xv = Xs[(rowg * 8 + r) * 64 + k];
                acc[r].x += xv * w.x;
                acc[r].y += xv * w.y;
                acc[r].z += xv * w.z;
                acc[r].w += xv * w.w;
            }
        }
        __syncthreads();
    }

    float4* out4 = (float4*)g_h;
#pragma unroll
    for (int r = 0; r < 8; r++) {
        int gr = r0 + rowg * 8 + r;
        if (gr < NN) out4[gr * 32 + colg] = acc[r];
    }
}

// ---------------- per-node alphas + init of emax/denom/out ----------------
// warp per node; lane covers 4 channels
__global__ __launch_bounds__(256) void k_alpha(const float* __restrict__ as,
                                               const float* __restrict__ ad) {
    int gw = (blockIdx.x * blockDim.x + threadIdx.x) >> 5;
    int lane = threadIdx.x & 31;
    if (gw >= NN) return;

    float4 hv = ((const float4*)g_h)[gw * 32 + lane];
    float4 a1 = ((const float4*)as)[lane];   // as[(lane/8)*32 + (lane%8)*4 ..] == as4[lane]
    float4 a2 = ((const float4*)ad)[lane];
    float ps = hv.x * a1.x + hv.y * a1.y + hv.z * a1.z + hv.w * a1.w;
    float pd = hv.x * a2.x + hv.y * a2.y + hv.z * a2.z + hv.w * a2.w;
#pragma unroll
    for (int off = 4; off; off >>= 1) {
        ps += __shfl_xor_sync(0xffffffffu, ps, off);
        pd += __shfl_xor_sync(0xffffffffu, pd, off);
    }
    ((float4*)g_out)[gw * 32 + lane] = make_float4(0.f, 0.f, 0.f, 0.f);
    if ((lane & 7) == 0) {
        int hd = lane >> 3;
        g_asrc[gw * 4 + hd]  = ps;
        g_adst[gw * 4 + hd]  = pd;
        g_emaxu[gw * 4 + hd] = ENC_NEGINF;
        g_denom[gw * 4 + hd] = 0.f;
    }
}

// ---------------- edge pass A: segment max ----------------
__global__ __launch_bounds__(256) void k_emax(const void* __restrict__ ei) {
    int e = blockIdx.x * blockDim.x + threadIdx.x;
    if (e >= ETOT) return;
    int s, d;
    edge_sd(ei, e, g_is64, s, d);
    float4 a = ((const float4*)g_asrc)[s];
    float4 b = ((const float4*)g_adst)[d];
    unsigned* em = &g_emaxu[d * 4];
    atomicMax(&em[0], fenc(lrelu(a.x + b.x)));
    atomicMax(&em[1], fenc(lrelu(a.y + b.y)));
    atomicMax(&em[2], fenc(lrelu(a.z + b.z)));
    atomicMax(&em[3], fenc(lrelu(a.w + b.w)));
}

// ---------------- edge pass B: segment sum of exp ----------------
__global__ __launch_bounds__(256) void k_esum(const void* __restrict__ ei) {
    int e = blockIdx.x * blockDim.x + threadIdx.x;
    if (e >= ETOT) return;
    int s, d;
    edge_sd(ei, e, g_is64, s, d);
    float4 a = ((const float4*)g_asrc)[s];
    float4 b = ((const float4*)g_adst)[d];
    uint4 mu = ((const uint4*)g_emaxu)[d];
    float vx = expf(lrelu(a.x + b.x) - fdec(mu.x));
    float vy = expf(lrelu(a.y + b.y) - fdec(mu.y));
    float vz = expf(lrelu(a.z + b.z) - fdec(mu.z));
    float vw = expf(lrelu(a.w + b.w) - fdec(mu.w));
    red_add_v4(&g_denom[d * 4], vx, vy, vz, vw);
}

// ---------------- edge pass C: weighted aggregation (warp per edge) ----------------
__global__ __launch_bounds__(256) void k_eaggr(const void* __restrict__ ei) {
    int gw = (blockIdx.x * blockDim.x + threadIdx.x) >> 5;
    int lane = threadIdx.x & 31;
    if (gw >= ETOT) return;
    int s, d;
    edge_sd(ei, gw, g_is64, s, d);
    float4 a  = ((const float4*)g_asrc)[s];
    float4 b  = ((const float4*)g_adst)[d];
    uint4  mu = ((const uint4*)g_emaxu)[d];
    float4 dn = ((const float4*)g_denom)[d];
    float at0 = expf(lrelu(a.x + b.x) - fdec(mu.x)) / dn.x;
    float at1 = expf(lrelu(a.y + b.y) - fdec(mu.y)) / dn.y;
    float at2 = expf(lrelu(a.z + b.z) - fdec(mu.z)) / dn.z;
    float at3 = expf(lrelu(a.w + b.w) - fdec(mu.w)) / dn.w;
    float attn = (lane < 16) ? (lane < 8 ? at0 : at1) : (lane < 24 ? at2 : at3);

    float4 hv = ((const float4*)g_h)[s * 32 + lane];
    red_add_v4(&g_out[d * 128 + lane * 4],
               hv.x * attn, hv.y * attn, hv.z * attn, hv.w * attn);
}

// ---------------- global max pool (post relu(out + b2)) ----------------
__global__ __launch_bounds__(256) void k_pool(const void* __restrict__ batch,
                                              const float* __restrict__ b2) {
    int i = blockIdx.x * blockDim.x + threadIdx.x;   // n*32 + c
    if (i >= NN * 32) return;
    int n = i >> 5, c = i & 31;
    int g = g_is64 ? (int)((const long long*)batch)[n] : ((const int*)batch)[n];
    float4 v  = ((const float4*)g_out)[i];
    float4 bb = ((const float4*)b2)[c];
    v.x = fmaxf(v.x + bb.x, 0.f);
    v.y = fmaxf(v.y + bb.y, 0.f);
    v.z = fmaxf(v.z + bb.z, 0.f);
    v.w = fmaxf(v.w + bb.w, 0.f);
    // values >= 0 -> int compare == float compare; pool init 0 matches isfinite guard
    int* pp = (int*)&g_pool[g * 128 + c * 4];
    atomicMax(&pp[0], __float_as_int(v.x));
    atomicMax(&pp[1], __float_as_int(v.y));
    atomicMax(&pp[2], __float_as_int(v.z));
    atomicMax(&pp[3], __float_as_int(v.w));
}

// ---------------- MLP tail ----------------
__global__ __launch_bounds__(256) void k_lin1(const float* __restrict__ Wlin,
                                              const float* __restrict__ blin) {
    __shared__ float sp[128];
    int g = blockIdx.x, t = threadIdx.x;
    if (t < 128) sp[t] = g_pool[g * 128 + t];
    __syncthreads();
    float acc = blin[t];
    for (int k = 0; k < 128; k++) acc += sp[k] * Wlin[k * 256 + t];
    g_z[g * 256 + t] = acc;
}

__global__ void k_lin2(const float* __restrict__ Wout,
                       const float* __restrict__ bout,
                       float* __restrict__ out) {
    int t = threadIdx.x;
    if (t >= GG * OUTW) return;
    int g = t / OUTW, o = t % OUTW;
    float acc = bout[o];
    const float* zr = &g_z[g * 256];
    for (int k = 0; k < 256; k++) acc += zr[k] * Wout[k * OUTW + o];
    out[t] = acc;
}

// ---------------- host launcher ----------------
extern "C" void kernel_launch(void* const* d_in, const int* in_sizes, int n_in,
                              void* d_out, int out_size) {
    const float* x    = (const float*)d_in[0];
    const void*  ei   = d_in[1];
    const void*  batch= d_in[2];
    const float* W0   = (const float*)d_in[3];
    const float* as0  = (const float*)d_in[4];
    const float* ad0  = (const float*)d_in[5];
    const float* b0   = (const float*)d_in[6];
    const float* W1   = (const float*)d_in[7];
    const float* as1  = (const float*)d_in[8];
    const float* ad1  = (const float*)d_in[9];
    const float* b1   = (const float*)d_in[10];
    const float* W2   = (const float*)d_in[11];
    const float* as2  = (const float*)d_in[12];
    const float* ad2  = (const float*)d_in[13];
    const float* b2   = (const float*)d_in[14];
    const float* Wlin = (const float*)d_in[15];
    const float* blin = (const float*)d_in[16];
    const float* Wout = (const float*)d_in[17];
    const float* bout = (const float*)d_in[18];

    const float* Ws[3]  = {W0, W1, W2};
    const float* ass[3] = {as0, as1, as2};
    const float* ads[3] = {ad0, ad1, ad2};
    const float* bp[3]  = {nullptr, b0, b1};   // previous layer's bias (input transform)

    k_detect<<<1, 1>>>((const unsigned*)ei);
    k_initpool<<<(GG * HCW + 255) / 256, 256>>>();

    const int gemm_blocks = (NN + 63) / 64;
    const int node_warps  = (NN * 32 + 255) / 256;
    const int edge_blocks = (ETOT + 255) / 256;
    const int aggr_blocks = (ETOT * 32 + 255) / 256;

    for (int l = 0; l < 3; l++) {
        k_gemm<<<gemm_blocks, 256>>>(x, Ws[l], bp[l], (l != 0) ? 1 : 0);
        k_alpha<<<node_warps, 256>>>(ass[l], ads[l]);
        k_emax<<<edge_blocks, 256>>>(ei);
        k_esum<<<edge_blocks, 256>>>(ei);
        k_eaggr<<<aggr_blocks, 256>>>(ei);
    }

    k_pool<<<(NN * 32 + 255) / 256, 256>>>(batch, b2);
    k_lin1<<<GG, 256>>>(Wlin, blin);
    k_lin2<<<1, GG * OUTW>>>(Wout, bout, (float*)d_out);
}

// round 7
// speedup vs baseline: 1.3979x; 1.3979x over previous
#include <cuda_runtime.h>
#include <cuda_bf16.h>
#include <math.h>

// ---------------- problem constants ----------------
#define NN    50000
#define EE    800000
#define FF    128
#define HH    4
#define CC    32
#define HCW   128
#define LINW  256
#define OUTW  10
#define GG    64
#define NEG   0.2f

// ---------------- device scratch (no allocation allowed) ----------------
__device__ float    g_h[NN * HCW];       // per-layer transformed features h = in @ W
__device__ float    g_out[NN * HCW];     // aggregated output (next layer's input)
__device__ float    g_asrc[NN * HH];
__device__ float    g_adst[NN * HH];
__device__ float    g_pool[GG * HCW];
__device__ float    g_z[GG * LINW];
__device__ int      g_is64;
__device__ unsigned g_gmax_enc;          // global max of asrc, monotone-encoded
// CSR of incoming edges (self-loops handled analytically)
__device__ int      g_deg[NN];           // histogram, then scatter cursor
__device__ int      g_row[NN + 1];
__device__ int      g_csr[EE];           // src node per incoming edge, grouped by dst

// ---------------- helpers ----------------
__device__ __forceinline__ float lrelu(float x) { return x > 0.f ? x : NEG * x; }

// monotone order-preserving float<->uint map for atomicMax
__device__ __forceinline__ unsigned fenc(float f) {
    unsigned u = __float_as_uint(f);
    return (u & 0x80000000u) ? ~u : (u | 0x80000000u);
}
__device__ __forceinline__ float fdec(unsigned u) {
    return __uint_as_float((u & 0x80000000u) ? (u & 0x7fffffffu) : ~u);
}
#define ENC_NEGINF 0x007fffffu

__device__ __forceinline__ int edge_idx(const void* __restrict__ ei, long long pos, int is64) {
    return is64 ? (int)((const long long*)ei)[pos] : ((const int*)ei)[pos];
}

// ---------------- dtype detection (int64 vs int32 indices) ----------------
__global__ void k_detect(const unsigned* __restrict__ ei_words) {
    unsigned acc = 0;
    for (int i = 1; i < 256; i += 2) acc |= ei_words[i];
    g_is64 = (acc == 0u) ? 1 : 0;
}

// zero pool + degree histogram
__global__ void k_init() {
    int i = blockIdx.x * blockDim.x + threadIdx.x;
    if (i < NN) g_deg[i] = 0;
    if (i < GG * HCW) g_pool[i] = 0.f;
}

// ---------------- CSR build ----------------
__global__ __launch_bounds__(256) void k_hist(const void* __restrict__ ei) {
    int e = blockIdx.x * blockDim.x + threadIdx.x;
    if (e >= EE) return;
    int d = edge_idx(ei, (long long)EE + e, g_is64);
    atomicAdd(&g_deg[d], 1);
}

#define SCAN_T 1024
#define SCAN_CHUNK ((NN + SCAN_T - 1) / SCAN_T)   // 49
__global__ __launch_bounds__(SCAN_T) void k_scan() {
    __shared__ int sums[SCAN_T];
    int t = threadIdx.x;
    int lo = t * SCAN_CHUNK;
    int hi = lo + SCAN_CHUNK; if (hi > NN) hi = NN;
    int s = 0;
    for (int i = lo; i < hi; i++) s += g_deg[i];
    sums[t] = s;
    __syncthreads();
    // Hillis-Steele inclusive scan
    for (int off = 1; off < SCAN_T; off <<= 1) {
        int v = (t >= off) ? sums[t - off] : 0;
        __syncthreads();
        sums[t] += v;
        __syncthreads();
    }
    int run = (t == 0) ? 0 : sums[t - 1];
    for (int i = lo; i < hi; i++) {
        run += g_deg[i];
        g_row[i + 1] = run;
        g_deg[i] = 0;         // reuse as scatter cursor
    }
    if (t == 0) g_row[0] = 0;
}

__global__ __launch_bounds__(256) void k_scatter(const void* __restrict__ ei) {
    int e = blockIdx.x * blockDim.x + threadIdx.x;
    if (e >= EE) return;
    int is64 = g_is64;
    int s = edge_idx(ei, e, is64);
    int d = edge_idx(ei, (long long)EE + e, is64);
    int pos = g_row[d] + atomicAdd(&g_deg[d], 1);
    g_csr[pos] = s;
}

// ---------------- GEMM: g_h = f(in) @ W,  f = identity or relu(x + bias_prev) ----------------
__global__ __launch_bounds__(256) void k_gemm(const float* __restrict__ inp,
                                              const float* __restrict__ W,
                                              const float* __restrict__ bias,
                                              int use_gout) {
    __shared__ float Ws[64 * 128];   // 32 KB
    __shared__ float Xs[64 * 64];    // 16 KB

    if (blockIdx.x == 0 && threadIdx.x == 0) g_gmax_enc = ENC_NEGINF; // reset for k_alpha

    const float* in = use_gout ? g_out : inp;
    const int tid  = threadIdx.x;
    const int r0   = blockIdx.x * 64;
    const int colg = tid & 31;
    const int rowg = tid >> 5;

    float4* Ws4 = (float4*)Ws;
    float4* Xs4 = (float4*)Xs;
    const float4* W4  = (const float4*)W;
    const float4* in4 = (const float4*)in;
    const float4* b4  = (const float4*)bias;

    float4 acc[8];
#pragma unroll
    for (int r = 0; r < 8; r++) acc[r] = make_float4(0.f, 0.f, 0.f, 0.f);

    for (int kk = 0; kk < 128; kk += 64) {
        for (int i = tid; i < 2048; i += 256) Ws4[i] = W4[kk * 32 + i];
        for (int i = tid; i < 1024; i += 256) {
            int row = i >> 4, kc = i & 15;
            int gr = r0 + row;
            float4 v = make_float4(0.f, 0.f, 0.f, 0.f);
            if (gr < NN) {
                v = in4[gr * 32 + (kk >> 2) + kc];
                if (bias) {
                    float4 bb = b4[(kk >> 2) + kc];
                    v.x = fmaxf(v.x + bb.x, 0.f);
                    v.y = fmaxf(v.y + bb.y, 0.f);
                    v.z = fmaxf(v.z + bb.z, 0.f);
                    v.w = fmaxf(v.w + bb.w, 0.f);
                }
            }
            Xs4[i] = v;
        }
        __syncthreads();

        for (int k = 0; k < 64; k++) {
            float4 w = Ws4[k * 32 + colg];
#pragma unroll
            for (int r = 0; r < 8; r++) {
                float xv = Xs[(rowg * 8 + r) * 64 + k];
                acc[r].x += xv * w.x;
                acc[r].y += xv * w.y;
                acc[r].z += xv * w.z;
                acc[r].w += xv * w.w;
            }
        }
        __syncthreads();
    }

    float4* out4 = (float4*)g_h;
#pragma unroll
    for (int r = 0; r < 8; r++) {
        int gr = r0 + rowg * 8 + r;
        if (gr < NN) out4[gr * 32 + colg] = acc[r];
    }
}

// ---------------- per-node alphas + global max of asrc ----------------
__global__ __launch_bounds__(256) void k_alpha(const float* __restrict__ as,
                                               const float* __restrict__ ad) {
    int gw = (blockIdx.x * blockDim.x + threadIdx.x) >> 5;
    int lane = threadIdx.x & 31;
    if (gw >= NN) return;

    float4 hv = ((const float4*)g_h)[gw * 32 + lane];
    float4 a1 = ((const float4*)as)[lane];
    float4 a2 = ((const float4*)ad)[lane];
    float ps = hv.x * a1.x + hv.y * a1.y + hv.z * a1.z + hv.w * a1.w;
    float pd = hv.x * a2.x + hv.y * a2.y + hv.z * a2.z + hv.w * a2.w;
#pragma unroll
    for (int off = 4; off; off >>= 1) {
        ps += __shfl_xor_sync(0xffffffffu, ps, off);
        pd += __shfl_xor_sync(0xffffffffu, pd, off);
    }
    if ((lane & 7) == 0) {
        int hd = lane >> 3;
        g_asrc[gw * 4 + hd] = ps;
        g_adst[gw * 4 + hd] = pd;
    }
    // warp max of the 4 head values of ps -> one atomic per warp
    float v = ((lane & 7) == 0) ? ps : -INFINITY;
    v = fmaxf(v, __shfl_xor_sync(0xffffffffu, v, 16));
    v = fmaxf(v, __shfl_xor_sync(0xffffffffu, v, 8));
    if (lane == 0) atomicMax(&g_gmax_enc, fenc(v));
}

// ---------------- fused softmax + aggregation: warp per destination node ----------------
// attn shift m = lrelu(gmax + adst[d]) is a per-dst upper bound on e (lrelu monotone),
// so exp args <= 0; softmax ratio is invariant to the shift.
__global__ __launch_bounds__(256) void k_aggr() {
    int w = (blockIdx.x * blockDim.x + threadIdx.x) >> 5;
    int lane = threadIdx.x & 31;
    if (w >= NN) return;
    int hd = lane >> 3;

    float gmax = fdec(g_gmax_enc);
    float adv  = g_adst[w * 4 + hd];
    float m    = lrelu(gmax + adv);

    int beg = g_row[w], end = g_row[w + 1];
    float4 acc = make_float4(0.f, 0.f, 0.f, 0.f);
    float den = 0.f;
    const float4* h4 = (const float4*)g_h;

    for (int base = beg; base < end; base += 32) {
        int j = base + lane;
        int sL = (j < end) ? g_csr[j] : 0;
        int cnt = end - base; if (cnt > 32) cnt = 32;
        for (int t = 0; t < cnt; t++) {
            int s = __shfl_sync(0xffffffffu, sL, t);
            float asv = g_asrc[s * 4 + hd];
            float ex  = __expf(lrelu(asv + adv) - m);
            float4 hv = h4[s * 32 + lane];
            den   += ex;
            acc.x += ex * hv.x;
            acc.y += ex * hv.y;
            acc.z += ex * hv.z;
            acc.w += ex * hv.w;
        }
    }
    // self loop (s = d)
    {
        float asv = g_asrc[w * 4 + hd];
        float ex  = __expf(lrelu(asv + adv) - m);
        float4 hv = h4[w * 32 + lane];
        den   += ex;
        acc.x += ex * hv.x;
        acc.y += ex * hv.y;
        acc.z += ex * hv.z;
        acc.w += ex * hv.w;
    }
    float inv = 1.f / den;
    ((float4*)g_out)[w * 32 + lane] =
        make_float4(acc.x * inv, acc.y * inv, acc.z * inv, acc.w * inv);
}

// ---------------- global max pool (post relu(out + b2)) ----------------
__global__ __launch_bounds__(256) void k_pool(const void* __restrict__ batch,
                                              const float* __restrict__ b2) {
    int i = blockIdx.x * blockDim.x + threadIdx.x;   // n*32 + c
    if (i >= NN * 32) return;
    int n = i >> 5, c = i & 31;
    int g = g_is64 ? (int)((const long long*)batch)[n] : ((const int*)batch)[n];
    float4 v  = ((const float4*)g_out)[i];
    float4 bb = ((const float4*)b2)[c];
    v.x = fmaxf(v.x + bb.x, 0.f);
    v.y = fmaxf(v.y + bb.y, 0.f);
    v.z = fmaxf(v.z + bb.z, 0.f);
    v.w = fmaxf(v.w + bb.w, 0.f);
    int* pp = (int*)&g_pool[g * 128 + c * 4];
    atomicMax(&pp[0], __float_as_int(v.x));
    atomicMax(&pp[1], __float_as_int(v.y));
    atomicMax(&pp[2], __float_as_int(v.z));
    atomicMax(&pp[3], __float_as_int(v.w));
}

// ---------------- MLP tail ----------------
__global__ __launch_bounds__(256) void k_lin1(const float* __restrict__ Wlin,
                                              const float* __restrict__ blin) {
    __shared__ float sp[128];
    int g = blockIdx.x, t = threadIdx.x;
    if (t < 128) sp[t] = g_pool[g * 128 + t];
    __syncthreads();
    float acc = blin[t];
    for (int k = 0; k < 128; k++) acc += sp[k] * Wlin[k * 256 + t];
    g_z[g * 256 + t] = acc;
}

__global__ void k_lin2(const float* __restrict__ Wout,
                       const float* __restrict__ bout,
                       float* __restrict__ out) {
    int t = threadIdx.x;
    if (t >= GG * OUTW) return;
    int g = t / OUTW, o = t % OUTW;
    float acc = bout[o];
    const float* zr = &g_z[g * 256];
    for (int k = 0; k < 256; k++) acc += zr[k] * Wout[k * OUTW + o];
    out[t] = acc;
}

// ---------------- host launcher ----------------
extern "C" void kernel_launch(void* const* d_in, const int* in_sizes, int n_in,
                              void* d_out, int out_size) {
    const float* x    = (const float*)d_in[0];
    const void*  ei   = d_in[1];
    const void*  batch= d_in[2];
    const float* W0   = (const float*)d_in[3];
    const float* as0  = (const float*)d_in[4];
    const float* ad0  = (const float*)d_in[5];
    const float* b0   = (const float*)d_in[6];
    const float* W1   = (const float*)d_in[7];
    const float* as1  = (const float*)d_in[8];
    const float* ad1  = (const float*)d_in[9];
    const float* b1   = (const float*)d_in[10];
    const float* W2   = (const float*)d_in[11];
    const float* as2  = (const float*)d_in[12];
    const float* ad2  = (const float*)d_in[13];
    const float* b2   = (const float*)d_in[14];
    const float* Wlin = (const float*)d_in[15];
    const float* blin = (const float*)d_in[16];
    const float* Wout = (const float*)d_in[17];
    const float* bout = (const float*)d_in[18];

    const float* Ws[3]  = {W0, W1, W2};
    const float* ass[3] = {as0, as1, as2};
    const float* ads[3] = {ad0, ad1, ad2};
    const float* bp[3]  = {nullptr, b0, b1};

    k_detect<<<1, 1>>>((const unsigned*)ei);
    k_init<<<(NN + 255) / 256, 256>>>();
    k_hist<<<(EE + 255) / 256, 256>>>(ei);
    k_scan<<<1, SCAN_T>>>();
    k_scatter<<<(EE + 255) / 256, 256>>>(ei);

    const int gemm_blocks = (NN + 63) / 64;
    const int node_warps  = (NN * 32 + 255) / 256;

    for (int l = 0; l < 3; l++) {
        k_gemm<<<gemm_blocks, 256>>>(x, Ws[l], bp[l], (l != 0) ? 1 : 0);
        k_alpha<<<node_warps, 256>>>(ass[l], ads[l]);
        k_aggr<<<node_warps, 256>>>();
    }

    k_pool<<<(NN * 32 + 255) / 256, 256>>>(batch, b2);
    k_lin1<<<GG, 256>>>(Wlin, blin);
    k_lin2<<<1, GG * OUTW>>>(Wout, bout, (float*)d_out);
}

// round 8
// speedup vs baseline: 1.9135x; 1.3688x over previous
#include <cuda_runtime.h>
#include <cuda_bf16.h>
#include <math.h>

// ---------------- problem constants ----------------
#define NN    50000
#define EE    800000
#define FF    128
#define HH    4
#define CC    32
#define HCW   128
#define LINW  256
#define OUTW  10
#define GG    64
#define NEG   0.2f
#define SB    ((NN + 1023) / 1024)   // 49 scan blocks

// ---------------- device scratch ----------------
__device__ float    g_h[NN * HCW];
__device__ float    g_out[NN * HCW];
__device__ float    g_asrc[NN * HH];
__device__ float    g_adst[NN * HH];
__device__ float    g_pool[GG * HCW];
__device__ float    g_z[GG * LINW];
__device__ int      g_is64;
__device__ unsigned g_gmax_enc[3];       // per-layer global max of asrc (encoded)
__device__ int      g_deg[NN];
__device__ int      g_row[NN + 1];
__device__ int      g_csr[EE];
__device__ int      g_bsum[SB];
__device__ int      g_boff[SB];

// ---------------- helpers ----------------
__device__ __forceinline__ float lrelu(float x) { return x > 0.f ? x : NEG * x; }

__device__ __forceinline__ unsigned fenc(float f) {
    unsigned u = __float_as_uint(f);
    return (u & 0x80000000u) ? ~u : (u | 0x80000000u);
}
__device__ __forceinline__ float fdec(unsigned u) {
    return __uint_as_float((u & 0x80000000u) ? (u & 0x7fffffffu) : ~u);
}
#define ENC_NEGINF 0x007fffffu

__device__ __forceinline__ int edge_idx(const void* __restrict__ ei, long long pos, int is64) {
    return is64 ? (int)((const long long*)ei)[pos] : ((const int*)ei)[pos];
}

// packed fp32x2 helpers
__device__ __forceinline__ unsigned long long pk2(float a, float b) {
    unsigned long long r;
    asm("mov.b64 %0, {%1,%2};" : "=l"(r) : "f"(a), "f"(b));
    return r;
}
__device__ __forceinline__ void upk2(unsigned long long v, float& a, float& b) {
    asm("mov.b64 {%0,%1}, %2;" : "=f"(a), "=f"(b) : "l"(v));
}
__device__ __forceinline__ void fma2(unsigned long long& d,
                                     unsigned long long a, unsigned long long b) {
    asm("fma.rn.f32x2 %0, %1, %2, %0;" : "+l"(d) : "l"(a), "l"(b));
}

// ---------------- init: pool zero, deg zero, gmax reset, dtype detect ----------------
__global__ void k_init(const unsigned* __restrict__ ei_words) {
    int i = blockIdx.x * blockDim.x + threadIdx.x;
    if (i < NN) g_deg[i] = 0;
    if (i < GG * HCW) g_pool[i] = 0.f;
    if (i < 3) g_gmax_enc[i] = ENC_NEGINF;
    if (i == 0) {
        unsigned acc = 0;
        for (int j = 1; j < 256; j += 2) acc |= ei_words[j];
        g_is64 = (acc == 0u) ? 1 : 0;
    }
}

// ---------------- CSR build ----------------
__global__ __launch_bounds__(256) void k_hist(const void* __restrict__ ei) {
    int e = blockIdx.x * blockDim.x + threadIdx.x;
    if (e >= EE) return;
    int d = edge_idx(ei, (long long)EE + e, g_is64);
    atomicAdd(&g_deg[d], 1);
}

__global__ __launch_bounds__(1024) void k_scan1() {
    __shared__ int s[1024];
    int t = threadIdx.x, i = blockIdx.x * 1024 + t;
    s[t] = (i < NN) ? g_deg[i] : 0;
    __syncthreads();
    for (int off = 512; off; off >>= 1) {
        if (t < off) s[t] += s[t + off];
        __syncthreads();
    }
    if (t == 0) g_bsum[blockIdx.x] = s[0];
}

__global__ void k_scan2() {
    __shared__ int s[SB];
    int t = threadIdx.x;
    if (t < SB) s[t] = g_bsum[t];
    __syncthreads();
    if (t == 0) {
        int run = 0;
        for (int b = 0; b < SB; b++) { g_boff[b] = run; run += s[b]; }
    }
}

__global__ __launch_bounds__(1024) void k_scan3() {
    __shared__ int s[1024];
    int t = threadIdx.x, i = blockIdx.x * 1024 + t;
    int v = (i < NN) ? g_deg[i] : 0;
    s[t] = v;
    __syncthreads();
    // inclusive Hillis-Steele
    for (int off = 1; off < 1024; off <<= 1) {
        int u = (t >= off) ? s[t - off] : 0;
        __syncthreads();
        s[t] += u;
        __syncthreads();
    }
    if (i < NN) {
        g_row[i + 1] = g_boff[blockIdx.x] + s[t];
        g_deg[i] = 0;                       // reuse as scatter cursor
    }
    if (i == 0) g_row[0] = 0;
}

__global__ __launch_bounds__(256) void k_scatter(const void* __restrict__ ei) {
    int e = blockIdx.x * blockDim.x + threadIdx.x;
    if (e >= EE) return;
    int is64 = g_is64;
    int s = edge_idx(ei, e, is64);
    int d = edge_idx(ei, (long long)EE + e, is64);
    int pos = g_row[d] + atomicAdd(&g_deg[d], 1);
    g_csr[pos] = s;
}

// ---------------- GEMM + fused alpha ----------------
// g_h = f(in) @ W with f = identity (layer 0) or relu(x + prev bias).
// Tile 128 rows x 128 cols, 256 threads, 8x8 per thread via fp32x2 packed FMA.
// Epilogue computes per-row alpha_src/alpha_dst (warp owns 16 full rows) and
// the block max of alpha_src for the softmax shift.
__global__ __launch_bounds__(256, 2) void k_gemm(const float* __restrict__ inp,
                                                 const float* __restrict__ W,
                                                 const float* __restrict__ bias,
                                                 int use_gout,
                                                 const float* __restrict__ as,
                                                 const float* __restrict__ ad,
                                                 int layer) {
    __shared__ float Ws[32 * 128];       // panel [k][n]
    __shared__ float Xs[128 * 33];       // [row][k], stride 33 (conflict-free bcast)

    const float* in = use_gout ? g_out : inp;
    const int tid = threadIdx.x;
    const int cg  = tid & 15;            // 8 cols: cg*8 .. cg*8+7
    const int rg  = tid >> 4;            // 8 rows: rg*8 .. rg*8+7
    const int r0  = blockIdx.x * 128;

    float4* Ws4 = (float4*)Ws;
    const float4* W4  = (const float4*)W;
    const float4* in4 = (const float4*)in;
    const float4* b4  = (const float4*)bias;

    unsigned long long acc2[8][4];
#pragma unroll
    for (int r = 0; r < 8; r++)
#pragma unroll
        for (int c = 0; c < 4; c++) acc2[r][c] = 0ull;

    for (int kk = 0; kk < 128; kk += 32) {
        // W panel: 32 k x 128 n = 1024 float4
#pragma unroll
        for (int i = tid; i < 1024; i += 256)
            Ws4[i] = W4[(kk + (i >> 5)) * 32 + (i & 31)];
        // X panel: 128 rows x 8 float4
#pragma unroll
        for (int i = tid; i < 1024; i += 256) {
            int row = i >> 3, j = i & 7;
            int gr = r0 + row;
            float4 v = make_float4(0.f, 0.f, 0.f, 0.f);
            if (gr < NN) {
                v = in4[gr * 32 + (kk >> 2) + j];
                if (bias) {
                    float4 bb = b4[(kk >> 2) + j];
                    v.x = fmaxf(v.x + bb.x, 0.f);
                    v.y = fmaxf(v.y + bb.y, 0.f);
                    v.z = fmaxf(v.z + bb.z, 0.f);
                    v.w = fmaxf(v.w + bb.w, 0.f);
                }
            }
            float* xp = &Xs[row * 33 + j * 4];
            xp[0] = v.x; xp[1] = v.y; xp[2] = v.z; xp[3] = v.w;
        }
        __syncthreads();

#pragma unroll
        for (int k = 0; k < 32; k++) {
            float4 wa = Ws4[k * 32 + cg * 2];
            float4 wb = Ws4[k * 32 + cg * 2 + 1];
            unsigned long long w0 = pk2(wa.x, wa.y);
            unsigned long long w1 = pk2(wa.z, wa.w);
            unsigned long long w2 = pk2(wb.x, wb.y);
            unsigned long long w3 = pk2(wb.z, wb.w);
#pragma unroll
            for (int r = 0; r < 8; r++) {
                float xv = Xs[(rg * 8 + r) * 33 + k];
                unsigned long long xp = pk2(xv, xv);
                fma2(acc2[r][0], xp, w0);
                fma2(acc2[r][1], xp, w1);
                fma2(acc2[r][2], xp, w2);
                fma2(acc2[r][3], xp, w3);
            }
        }
        __syncthreads();
    }

    // ---- epilogue: store h, compute alphas, block max ----
    const float4* as4 = (const float4*)as;
    const float4* ad4 = (const float4*)ad;
    float4 A0 = as4[cg * 2], A1 = as4[cg * 2 + 1];
    float4 D0 = ad4[cg * 2], D1 = ad4[cg * 2 + 1];
    float4* out4 = (float4*)g_h;
    float mxl = -INFINITY;
    const int head = cg >> 2;
    const bool lead = (cg & 3) == 0;

#pragma unroll
    for (int r = 0; r < 8; r++) {
        float a0, a1, a2, a3, a4, a5, a6, a7;
        upk2(acc2[r][0], a0, a1);
        upk2(acc2[r][1], a2, a3);
        upk2(acc2[r][2], a4, a5);
        upk2(acc2[r][3], a6, a7);
        float ps = a0 * A0.x + a1 * A0.y + a2 * A0.z + a3 * A0.w
                 + a4 * A1.x + a5 * A1.y + a6 * A1.z + a7 * A1.w;
        float pd = a0 * D0.x + a1 * D0.y + a2 * D0.z + a3 * D0.w
                 + a4 * D1.x + a5 * D1.y + a6 * D1.z + a7 * D1.w;
        ps += __shfl_xor_sync(0xffffffffu, ps, 1);
        ps += __shfl_xor_sync(0xffffffffu, ps, 2);
        pd += __shfl_xor_sync(0xffffffffu, pd, 1);
        pd += __shfl_xor_sync(0xffffffffu, pd, 2);
        int gr = r0 + rg * 8 + r;
        if (gr < NN) {
            out4[gr * 32 + cg * 2]     = make_float4(a0, a1, a2, a3);
            out4[gr * 32 + cg * 2 + 1] = make_float4(a4, a5, a6, a7);
            if (lead) {
                g_asrc[gr * 4 + head] = ps;
                g_adst[gr * 4 + head] = pd;
                mxl = fmaxf(mxl, ps);
            }
        }
    }

    __syncthreads();
    float* sred = Xs;     // reuse smem
    sred[tid] = mxl;
    __syncthreads();
    for (int s = 128; s; s >>= 1) {
        if (tid < s) sred[tid] = fmaxf(sred[tid], sred[tid + s]);
        __syncthreads();
    }
    if (tid == 0) atomicMax(&g_gmax_enc[layer], fenc(sred[0]));
}

// ---------------- fused softmax + aggregation: warp per destination node ----------------
__global__ __launch_bounds__(256) void k_aggr(int layer) {
    int w = (blockIdx.x * blockDim.x + threadIdx.x) >> 5;
    int lane = threadIdx.x & 31;
    if (w >= NN) return;
    int hd = lane >> 3;

    float gmax = fdec(g_gmax_enc[layer]);
    float adv  = g_adst[w * 4 + hd];
    float m    = lrelu(gmax + adv);

    int beg = g_row[w], end = g_row[w + 1];
    float4 acc = make_float4(0.f, 0.f, 0.f, 0.f);
    float den = 0.f;
    const float4* h4 = (const float4*)g_h;

    int base = beg;
    for (; base + 32 <= end; base += 32) {
        int sL = g_csr[base + lane];
#pragma unroll 8
        for (int t = 0; t < 32; t++) {
            int s = __shfl_sync(0xffffffffu, sL, t);
            float asv = g_asrc[s * 4 + hd];
            float ex  = __expf(lrelu(asv + adv) - m);
            float4 hv = h4[s * 32 + lane];
            den   += ex;
            acc.x += ex * hv.x;
            acc.y += ex * hv.y;
            acc.z += ex * hv.z;
            acc.w += ex * hv.w;
        }
    }
    if (base < end) {
        int sL = (base + lane < end) ? g_csr[base + lane] : 0;
        int cnt = end - base;
        for (int t = 0; t < cnt; t++) {
            int s = __shfl_sync(0xffffffffu, sL, t);
            float asv = g_asrc[s * 4 + hd];
            float ex  = __expf(lrelu(asv + adv) - m);
            float4 hv = h4[s * 32 + lane];
            den   += ex;
            acc.x += ex * hv.x;
            acc.y += ex * hv.y;
            acc.z += ex * hv.z;
            acc.w += ex * hv.w;
        }
    }
    // self loop
    {
        float asv = g_asrc[w * 4 + hd];
        float ex  = __expf(lrelu(asv + adv) - m);
        float4 hv = h4[w * 32 + lane];
        den   += ex;
        acc.x += ex * hv.x;
        acc.y += ex * hv.y;
        acc.z += ex * hv.z;
        acc.w += ex * hv.w;
    }
    float inv = 1.f / den;
    ((float4*)g_out)[w * 32 + lane] =
        make_float4(acc.x * inv, acc.y * inv, acc.z * inv, acc.w * inv);
}

// ---------------- global max pool (post relu(out + b2)) ----------------
__global__ __launch_bounds__(256) void k_pool(const void* __restrict__ batch,
                                              const float* __restrict__ b2) {
    int i = blockIdx.x * blockDim.x + threadIdx.x;
    if (i >= NN * 32) return;
    int n = i >> 5, c = i & 31;
    int g = g_is64 ? (int)((const long long*)batch)[n] : ((const int*)batch)[n];
    float4 v  = ((const float4*)g_out)[i];
    float4 bb = ((const float4*)b2)[c];
    v.x = fmaxf(v.x + bb.x, 0.f);
    v.y = fmaxf(v.y + bb.y, 0.f);
    v.z = fmaxf(v.z + bb.z, 0.f);
    v.w = fmaxf(v.w + bb.w, 0.f);
    int* pp = (int*)&g_pool[g * 128 + c * 4];
    atomicMax(&pp[0], __float_as_int(v.x));
    atomicMax(&pp[1], __float_as_int(v.y));
    atomicMax(&pp[2], __float_as_int(v.z));
    atomicMax(&pp[3], __float_as_int(v.w));
}

// ---------------- MLP tail ----------------
__global__ __launch_bounds__(256) void k_lin1(const float* __restrict__ Wlin,
                                              const float* __restrict__ blin) {
    __shared__ float sp[128];
    int g = blockIdx.x, t = threadIdx.x;
    if (t < 128) sp[t] = g_pool[g * 128 + t];
    __syncthreads();
    float acc = blin[t];
    for (int k = 0; k < 128; k++) acc += sp[k] * Wlin[k * 256 + t];
    g_z[g * 256 + t] = acc;
}

__global__ void k_lin2(const float* __restrict__ Wout,
                       const float* __restrict__ bout,
                       float* __restrict__ out) {
    int t = threadIdx.x;
    if (t >= GG * OUTW) return;
    int g = t / OUTW, o = t % OUTW;
    float acc = bout[o];
    const float* zr = &g_z[g * 256];
    for (int k = 0; k < 256; k++) acc += zr[k] * Wout[k * OUTW + o];
    out[t] = acc;
}

// ---------------- host launcher ----------------
extern "C" void kernel_launch(void* const* d_in, const int* in_sizes, int n_in,
                              void* d_out, int out_size) {
    const float* x    = (const float*)d_in[0];
    const void*  ei   = d_in[1];
    const void*  batch= d_in[2];
    const float* W0   = (const float*)d_in[3];
    const float* as0  = (const float*)d_in[4];
    const float* ad0  = (const float*)d_in[5];
    const float* b0   = (const float*)d_in[6];
    const float* W1   = (const float*)d_in[7];
    const float* as1  = (const float*)d_in[8];
    const float* ad1  = (const float*)d_in[9];
    const float* b1   = (const float*)d_in[10];
    const float* W2   = (const float*)d_in[11];
    const float* as2  = (const float*)d_in[12];
    const float* ad2  = (const float*)d_in[13];
    const float* b2   = (const float*)d_in[14];
    const float* Wlin = (const float*)d_in[15];
    const float* blin = (const float*)d_in[16];
    const float* Wout = (const float*)d_in[17];
    const float* bout = (const float*)d_in[18];

    const float* Ws[3]  = {W0, W1, W2};
    const float* ass[3] = {as0, as1, as2};
    const float* ads[3] = {ad0, ad1, ad2};
    const float* bp[3]  = {nullptr, b0, b1};

    k_init<<<(NN + 255) / 256, 256>>>((const unsigned*)ei);
    k_hist<<<(EE + 255) / 256, 256>>>(ei);
    k_scan1<<<SB, 1024>>>();
    k_scan2<<<1, 64>>>();
    k_scan3<<<SB, 1024>>>();
    k_scatter<<<(EE + 255) / 256, 256>>>(ei);

    const int gemm_blocks = (NN + 127) / 128;
    const int node_warps  = (NN * 32 + 255) / 256;

    for (int l = 0; l < 3; l++) {
        k_gemm<<<gemm_blocks, 256>>>(x, Ws[l], bp[l], (l != 0) ? 1 : 0,
                                     ass[l], ads[l], l);
        k_aggr<<<node_warps, 256>>>(l);
    }

    k_pool<<<(NN * 32 + 255) / 256, 256>>>(batch, b2);
    k_lin1<<<GG, 256>>>(Wlin, blin);
    k_lin2<<<1, GG * OUTW>>>(Wout, bout, (float*)d_out);
}